// round 6
// baseline (speedup 1.0000x reference)
#include <cuda_runtime.h>

#define N_NODE 50000
#define N_EDGE 800000
#define D_FEAT 64
#define N_M    11
#define DEPTH  3

#define SCAN_BLK 512
#define N_SBLK ((N_NODE + SCAN_BLK - 1) / SCAN_BLK)   // 98

// ---------------- device scratch (no allocations; zero-init at module load) ----
__device__ float    g_y[2][N_NODE * D_FEAT];   // S x, S^2 x
__device__ float    g_dinv[N_NODE];
__device__ unsigned g_cnt[N_NODE];             // counts; scatter drains back to 0
__device__ unsigned g_rowstart[N_NODE + 1];
__device__ volatile unsigned long long g_look[N_SBLK];  // lookback {val<<2|state}
__device__ int2     g_csr[N_EDGE];             // packed {col, val bits}, row-sorted
__device__ float    g_q[16];                   // q[L][k]

// ---------------- per-row edge counts + lookback-flag reset ----------------
__global__ __launch_bounds__(256) void count_kernel(const int* __restrict__ ei) {
    unsigned e = blockIdx.x * blockDim.x + threadIdx.x;
    if (e < N_SBLK) g_look[e] = 0ull;    // consumed only by the NEXT kernel
    if (e < N_EDGE) atomicAdd(&g_cnt[ei[e]], 1u);
}

// ---------------- single-launch decoupled-lookback exclusive scan ----------
// Produces g_rowstart (exclusive prefix of counts) and g_dinv. Counts left
// intact (scatter drains them back to zero for the next graph replay).
__global__ __launch_bounds__(SCAN_BLK) void scan_kernel() {
    __shared__ unsigned warp_sums[SCAN_BLK / 32];
    __shared__ unsigned s_excl;
    int t = threadIdx.x, b = blockIdx.x;
    int i = b * SCAN_BLK + t;
    unsigned v = (i < N_NODE) ? g_cnt[i] : 0u;

    // inclusive warp scan
    unsigned sc = v;
    #pragma unroll
    for (int o = 1; o < 32; o <<= 1) {
        unsigned n = __shfl_up_sync(0xffffffffu, sc, o);
        if ((t & 31) >= o) sc += n;
    }
    if ((t & 31) == 31) warp_sums[t >> 5] = sc;
    __syncthreads();
    if (t < SCAN_BLK / 32) {
        unsigned ws = warp_sums[t];
        #pragma unroll
        for (int o = 1; o < SCAN_BLK / 32; o <<= 1) {
            unsigned n = __shfl_up_sync(0xffffu, ws, o);
            if (t >= o) ws += n;
        }
        warp_sums[t] = ws;
    }
    __syncthreads();
    unsigned base = (t >= 32) ? warp_sums[(t >> 5) - 1] : 0u;
    unsigned incl = base + sc;

    if (t == 0) {
        unsigned total = warp_sums[SCAN_BLK / 32 - 1];
        if (b == 0) {
            g_look[0] = ((unsigned long long)total << 2) | 2ull;  // prefix
            s_excl = 0u;
        } else {
            g_look[b] = ((unsigned long long)total << 2) | 1ull;  // aggregate
            unsigned excl = 0u;
            int idx = b - 1;
            while (true) {
                unsigned long long fv = g_look[idx];
                unsigned st = (unsigned)(fv & 3ull);
                if (st == 2u) { excl += (unsigned)(fv >> 2); break; }
                if (st == 1u) { excl += (unsigned)(fv >> 2); idx--; }
            }
            g_look[b] = ((unsigned long long)(excl + total) << 2) | 2ull;
            s_excl = excl;
        }
    }
    __syncthreads();
    unsigned ex = s_excl;
    if (i < N_NODE) {
        g_rowstart[i] = ex + incl - v;
        g_dinv[i] = rsqrtf(v ? (float)v : 1.0f);
    }
    if (b == 0 && t == 0) g_rowstart[N_NODE] = N_EDGE;
}

// ---------------- scatter edges into packed CSR ----------------
// atomicSub drains g_cnt back to 0 (pre-launch state restored for replay).
__global__ __launch_bounds__(256) void scatter_kernel(const int* __restrict__ ei,
                                                       const float* __restrict__ attr) {
    unsigned e = blockIdx.x * blockDim.x + threadIdx.x;
    if (e >= N_EDGE) return;
    int r = ei[e];
    int c = ei[e + N_EDGE];
    float v = g_dinv[r] * attr[e] * g_dinv[c];
    unsigned old = atomicSub(&g_cnt[r], 1u);
    unsigned pos = g_rowstart[r] + old - 1u;
    g_csr[pos] = make_int2(c, __float_as_int(v));
}

// ---------------- polynomial coefficient table ----------------
// xs_hist[L][m] = sum_k p[L][m][k] * S^k x  (recurrence linear in S, xs0==x).
// l=-1, r=1 so (l+r)=0, (r-l)=2.
__global__ void coeff_kernel(const float* __restrict__ alphas,
                             const float* __restrict__ w,
                             const float* __restrict__ a_arr,
                             const float* __restrict__ b_arr) {
    if (threadIdx.x != 0 || blockIdx.x != 0) return;
    double q[4][4] = {};
    for (int m = 0; m < N_M; m++) {
        double a = a_arr[m], b = b_arr[m];
        double p[4][4] = {};
        p[0][0] = 1.0;
        double coef1 = (a - b) * 0.5;
        double coef2 = (a + b + 2.0) * 0.5;
        double al0 = alphas[0 * N_M + m];
        p[1][0] = al0 * coef1;
        p[1][1] = al0 * coef2;
        for (int L = 2; L <= DEPTH; L++) {
            double Lf = (double)L;
            double coef_l  = 2.0 * Lf * (Lf + a + b) * (2.0 * Lf - 2.0 + a + b);
            double c_lm1_1 = (2.0 * Lf + a + b - 1.0) * (2.0 * Lf + a + b) * (2.0 * Lf + a + b - 2.0);
            double c_lm1_2 = (2.0 * Lf + a + b - 1.0) * (a * a - b * b);
            double c_lm2   = 2.0 * (Lf - 1.0 + a) * (Lf - 1.0 + b) * (2.0 * Lf + a + b);
            double alL   = alphas[(L - 1) * N_M + m];
            double alLm1 = alphas[(L - 2) * N_M + m];
            double tmp1 = alL * (c_lm1_1 / coef_l);
            double tmp2 = alL * (c_lm1_2 / coef_l);
            double tmp3 = alL * alLm1 * (c_lm2 / coef_l);
            for (int k = 0; k <= L; k++) {
                double t = 0.0;
                if (k > 0) t += tmp1 * p[L - 1][k - 1];
                t -= tmp2 * p[L - 1][k];
                t -= tmp3 * p[L - 2][k];
                p[L][k] = t;
            }
        }
        double wm = w[m];
        for (int L = 0; L < 4; L++)
            for (int k = 0; k < 4; k++)
                q[L][k] += wm * p[L][k];
    }
    for (int i = 0; i < 16; i++) g_q[i] = (float)q[i / 4][i % 4];
}

// ---------------- CSR SpMM: ONE WARP PER ROW, float2 per lane, 4-way unroll --
// stage 0: x -> g_y[0];  stage 1: g_y[0] -> g_y[1].
// Scratch pointers resolved IN DEVICE CODE (host-side refs to __device__
// globals resolve to the host shadow symbol).
__global__ __launch_bounds__(256) void spmm_csr_kernel(const float2* __restrict__ xext,
                                                        int stage) {
    unsigned gid = blockIdx.x * blockDim.x + threadIdx.x;
    unsigned row = gid >> 5;
    if (row >= N_NODE) return;
    unsigned lane = gid & 31u;
    const float2* __restrict__ xin =
        (stage == 0) ? xext : (const float2*)g_y[0];
    float2* yout = (float2*)g_y[stage];

    unsigned s = g_rowstart[row], e = g_rowstart[row + 1];
    float2 a0 = {0.f,0.f}, a1 = {0.f,0.f}, a2 = {0.f,0.f}, a3 = {0.f,0.f};
    unsigned i = s;
    for (; i + 4 <= e; i += 4) {
        int2 p0 = __ldg(g_csr + i);
        int2 p1 = __ldg(g_csr + i + 1);
        int2 p2 = __ldg(g_csr + i + 2);
        int2 p3 = __ldg(g_csr + i + 3);
        float2 x0 = __ldg(xin + (unsigned)p0.x * 32u + lane);
        float2 x1 = __ldg(xin + (unsigned)p1.x * 32u + lane);
        float2 x2 = __ldg(xin + (unsigned)p2.x * 32u + lane);
        float2 x3 = __ldg(xin + (unsigned)p3.x * 32u + lane);
        float v0 = __int_as_float(p0.y), v1 = __int_as_float(p1.y);
        float v2 = __int_as_float(p2.y), v3 = __int_as_float(p3.y);
        a0.x += v0*x0.x; a0.y += v0*x0.y;
        a1.x += v1*x1.x; a1.y += v1*x1.y;
        a2.x += v2*x2.x; a2.y += v2*x2.y;
        a3.x += v3*x3.x; a3.y += v3*x3.y;
    }
    for (; i < e; i++) {
        int2 p0 = __ldg(g_csr + i);
        float2 x0 = __ldg(xin + (unsigned)p0.x * 32u + lane);
        float v0 = __int_as_float(p0.y);
        a0.x += v0*x0.x; a0.y += v0*x0.y;
    }
    a0.x += a1.x + a2.x + a3.x;
    a0.y += a1.y + a2.y + a3.y;
    yout[row * 32u + lane] = a0;
}

// ---------------- final CSR SpMM (S^3 x) fused with output combine ----------
// out[n,L,:] = sum_k q[L][k] * (S^k x)[n,:],  out shape (N_NODE, 4, 64) f32
__global__ __launch_bounds__(256) void spmm_final_kernel(const float2* __restrict__ x,
                                                          float2* __restrict__ out) {
    unsigned gid = blockIdx.x * blockDim.x + threadIdx.x;
    unsigned row = gid >> 5;
    if (row >= N_NODE) return;
    unsigned lane = gid & 31u;
    unsigned s = g_rowstart[row], e = g_rowstart[row + 1];
    const float2* __restrict__ y1 = (const float2*)g_y[1];   // S^2 x
    float2 a0 = {0.f,0.f}, a1c = {0.f,0.f}, a2c = {0.f,0.f}, a3c = {0.f,0.f};
    unsigned i = s;
    for (; i + 4 <= e; i += 4) {
        int2 p0 = __ldg(g_csr + i);
        int2 p1 = __ldg(g_csr + i + 1);
        int2 p2 = __ldg(g_csr + i + 2);
        int2 p3 = __ldg(g_csr + i + 3);
        float2 x0 = __ldg(y1 + (unsigned)p0.x * 32u + lane);
        float2 x1 = __ldg(y1 + (unsigned)p1.x * 32u + lane);
        float2 x2 = __ldg(y1 + (unsigned)p2.x * 32u + lane);
        float2 x3 = __ldg(y1 + (unsigned)p3.x * 32u + lane);
        float v0 = __int_as_float(p0.y), v1 = __int_as_float(p1.y);
        float v2 = __int_as_float(p2.y), v3 = __int_as_float(p3.y);
        a0.x  += v0*x0.x; a0.y  += v0*x0.y;
        a1c.x += v1*x1.x; a1c.y += v1*x1.y;
        a2c.x += v2*x2.x; a2c.y += v2*x2.y;
        a3c.x += v3*x3.x; a3c.y += v3*x3.y;
    }
    for (; i < e; i++) {
        int2 p0 = __ldg(g_csr + i);
        float2 x0 = __ldg(y1 + (unsigned)p0.x * 32u + lane);
        float v0 = __int_as_float(p0.y);
        a0.x += v0*x0.x; a0.y += v0*x0.y;
    }
    float2 s3;
    s3.x = a0.x + a1c.x + a2c.x + a3c.x;
    s3.y = a0.y + a1c.y + a2c.y + a3c.y;

    unsigned idx = row * 32u + lane;
    float2 x0 = __ldg(x + idx);
    float2 s1 = ((const float2*)g_y[0])[idx];
    float2 s2 = ((const float2*)g_y[1])[idx];

    float q00 = g_q[0];
    float q10 = g_q[4],  q11 = g_q[5];
    float q20 = g_q[8],  q21 = g_q[9],  q22 = g_q[10];
    float q30 = g_q[12], q31 = g_q[13], q32 = g_q[14], q33 = g_q[15];

    float2 o0, o1, o2, o3;
    o0.x = q00*x0.x;                                      o0.y = q00*x0.y;
    o1.x = q10*x0.x + q11*s1.x;                           o1.y = q10*x0.y + q11*s1.y;
    o2.x = q20*x0.x + q21*s1.x + q22*s2.x;                o2.y = q20*x0.y + q21*s1.y + q22*s2.y;
    o3.x = q30*x0.x + q31*s1.x + q32*s2.x + q33*s3.x;     o3.y = q30*x0.y + q31*s1.y + q32*s2.y + q33*s3.y;

    // out (N_NODE, 4, 64) f32 -> float2 index row*128 + L*32 + lane
    unsigned base = row * 128u + lane;
    out[base +  0u] = o0;
    out[base + 32u] = o1;
    out[base + 64u] = o2;
    out[base + 96u] = o3;
}

// ---------------- launch ----------------
extern "C" void kernel_launch(void* const* d_in, const int* in_sizes, int n_in,
                              void* d_out, int out_size) {
    const float* x      = (const float*)d_in[0];
    const int*   ei     = (const int*)  d_in[1];
    const float* attr   = (const float*)d_in[2];
    const float* alphas = (const float*)d_in[3];
    const float* w      = (const float*)d_in[4];
    const float* a_arr  = (const float*)d_in[5];
    const float* b_arr  = (const float*)d_in[6];
    float* out = (float*)d_out;

    const unsigned rt = (unsigned)N_NODE * 32u;   // 1.6M threads, warp per row

    count_kernel<<<(N_EDGE + 255) / 256, 256>>>(ei);                 // idx 0
    scan_kernel<<<N_SBLK, SCAN_BLK>>>();                             // idx 1
    scatter_kernel<<<(N_EDGE + 255) / 256, 256>>>(ei, attr);         // idx 2
    spmm_csr_kernel<<<(rt + 255) / 256, 256>>>((const float2*)x, 0); // idx 3 (profiled)
    coeff_kernel<<<1, 32>>>(alphas, w, a_arr, b_arr);                // idx 4
    spmm_csr_kernel<<<(rt + 255) / 256, 256>>>((const float2*)x, 1); // idx 5
    spmm_final_kernel<<<(rt + 255) / 256, 256>>>((const float2*)x, (float2*)out);
}